// round 3
// baseline (speedup 1.0000x reference)
#include <cuda_runtime.h>

#define SEQ 2048
#define EMB 512
#define NH 8
#define DK 64
#define NB 4
#define NEGV -1000000000.0f

// Scratch (allocation-free rule: __device__ globals)
__device__ float g_q[(size_t)NB*NH*SEQ*DK];
__device__ float g_k[(size_t)NB*NH*SEQ*DK];
__device__ float g_v[(size_t)NB*NH*SEQ*DK];
__device__ float g_att[(size_t)NB*NH*SEQ*DK];

// ---------------------------------------------------------------------------
// Packed fp32x2 math (sm_103a): 2 FMAs per issue slot.
// ---------------------------------------------------------------------------
union F2U { float2 f; unsigned long long u; };

__device__ __forceinline__ float2 ffma2(float2 a, float2 b, float2 c) {
    F2U A, B, C, D; A.f = a; B.f = b; C.f = c;
    asm("fma.rn.f32x2 %0, %1, %2, %3;" : "=l"(D.u) : "l"(A.u), "l"(B.u), "l"(C.u));
    return D.f;
}
__device__ __forceinline__ float2 fmul2(float2 a, float2 b) {
    F2U A, B, D; A.f = a; B.f = b;
    asm("mul.rn.f32x2 %0, %1, %2;" : "=l"(D.u) : "l"(A.u), "l"(B.u));
    return D.f;
}

// ---------------------------------------------------------------------------
// Projection GEMM: C[m][n] = sum_k X[m][k]*W[n][k] + bias[n]
// M=8192, N=512, K=512. 128x128 tile, BK=16, 256 threads, 8x8 micro-tile
// with packed f32x2 accumulation (2 FLOP/smem-byte -> fma-bound).
// headLayout=1: store to [(b*8+h)*2048+s]*64+d
// ---------------------------------------------------------------------------
__global__ __launch_bounds__(256, 2) void proj_kernel(
    const float* __restrict__ X, const float* __restrict__ W,
    const float* __restrict__ bias, float* __restrict__ out, int headLayout)
{
    __shared__ float As[16][132];   // As[k][m]
    __shared__ float Bs[16][132];   // Bs[k][n]

    const int t  = threadIdx.x;
    const int tx = t & 15, ty = t >> 4;
    const int m0 = blockIdx.y * 128;
    const int n0 = blockIdx.x * 128;

    const int lrow = t >> 1;         // 0..127
    const int lk   = (t & 1) * 8;    // 0 or 8

    float2 acc[8][2][2];
    #pragma unroll
    for (int i = 0; i < 8; i++)
        #pragma unroll
        for (int g = 0; g < 2; g++) {
            acc[i][g][0] = make_float2(0.f, 0.f);
            acc[i][g][1] = make_float2(0.f, 0.f);
        }

    for (int k0 = 0; k0 < EMB; k0 += 16) {
        float4 a0 = *(const float4*)&X[(size_t)(m0 + lrow) * EMB + k0 + lk];
        float4 a1 = *(const float4*)&X[(size_t)(m0 + lrow) * EMB + k0 + lk + 4];
        float4 b0 = *(const float4*)&W[(size_t)(n0 + lrow) * EMB + k0 + lk];
        float4 b1 = *(const float4*)&W[(size_t)(n0 + lrow) * EMB + k0 + lk + 4];
        __syncthreads();
        As[lk + 0][lrow] = a0.x; As[lk + 1][lrow] = a0.y;
        As[lk + 2][lrow] = a0.z; As[lk + 3][lrow] = a0.w;
        As[lk + 4][lrow] = a1.x; As[lk + 5][lrow] = a1.y;
        As[lk + 6][lrow] = a1.z; As[lk + 7][lrow] = a1.w;
        Bs[lk + 0][lrow] = b0.x; Bs[lk + 1][lrow] = b0.y;
        Bs[lk + 2][lrow] = b0.z; Bs[lk + 3][lrow] = b0.w;
        Bs[lk + 4][lrow] = b1.x; Bs[lk + 5][lrow] = b1.y;
        Bs[lk + 6][lrow] = b1.z; Bs[lk + 7][lrow] = b1.w;
        __syncthreads();
        #pragma unroll
        for (int kk = 0; kk < 16; kk++) {
            float4 bv0 = *(const float4*)&Bs[kk][4 * tx];
            float4 bv1 = *(const float4*)&Bs[kk][64 + 4 * tx];
            float2 b00 = make_float2(bv0.x, bv0.y);
            float2 b01 = make_float2(bv0.z, bv0.w);
            float2 b10 = make_float2(bv1.x, bv1.y);
            float2 b11 = make_float2(bv1.z, bv1.w);
            #pragma unroll
            for (int i = 0; i < 8; i++) {
                const float av = As[kk][ty + 16 * i];
                const float2 aa = make_float2(av, av);
                acc[i][0][0] = ffma2(aa, b00, acc[i][0][0]);
                acc[i][0][1] = ffma2(aa, b01, acc[i][0][1]);
                acc[i][1][0] = ffma2(aa, b10, acc[i][1][0]);
                acc[i][1][1] = ffma2(aa, b11, acc[i][1][1]);
            }
        }
    }

    #pragma unroll
    for (int g = 0; g < 2; g++) {
        const int n = n0 + 64 * g + 4 * tx;
        const float4 bb = *(const float4*)&bias[n];
        #pragma unroll
        for (int i = 0; i < 8; i++) {
            const int m = m0 + ty + 16 * i;
            float4 c;
            c.x = acc[i][g][0].x + bb.x;
            c.y = acc[i][g][0].y + bb.y;
            c.z = acc[i][g][1].x + bb.z;
            c.w = acc[i][g][1].y + bb.w;
            if (headLayout) {
                const int bb_ = m >> 11, s = m & 2047, h = n >> 6, d = n & 63;
                *(float4*)&out[((size_t)((bb_ << 3) + h) * SEQ + s) * DK + d] = c;
            } else {
                *(float4*)&out[(size_t)m * EMB + n] = c;
            }
        }
    }
}

// ---------------------------------------------------------------------------
// Flash-style attention: one (b,h), 128-query tile, 64-key inner tiles.
// 256 threads, 8x4 micro-tile, packed f32x2. K stored transposed in smem so
// the key dimension is contiguous for packed pairs.
// ---------------------------------------------------------------------------
__global__ __launch_bounds__(256, 2) void attn_kernel(
    const float* __restrict__ Q, const float* __restrict__ K,
    const float* __restrict__ V, const int* __restrict__ mask,
    float* __restrict__ O)
{
    extern __shared__ float sm[];
    float* Qs = sm;              // 128 x 68  (row=query, col=dim)
    float* Kt = Qs + 128 * 68;   // 64 x 68   (row=dim,  col=key)   -- transposed
    float* Vs = Kt + 64 * 68;    // 64 x 68   (row=key,  col=dim)
    float* Ps = Vs + 64 * 68;    // 128 x 68  (row=query,col=key)

    const int t  = threadIdx.x;
    const int tx = t & 15, ty = t >> 4;
    const int bh = blockIdx.y;
    const int b  = bh >> 3;
    const int q0 = blockIdx.x * 128;

    const float* qp = Q + (size_t)bh * SEQ * DK;
    const float* kp = K + (size_t)bh * SEQ * DK;
    const float* vp = V + (size_t)bh * SEQ * DK;
    const int*   mp = mask + (size_t)b * SEQ * SEQ;

    // Load Q tile (128 x 64)
    {
        const int r = t & 127, c0 = (t >> 7) * 32;
        #pragma unroll
        for (int ci = 0; ci < 32; ci += 4)
            *(float4*)&Qs[r * 68 + c0 + ci] =
                *(const float4*)&qp[(size_t)(q0 + r) * DK + c0 + ci];
    }

    float2 o[8][2];
    float  m_[8], l_[8];
    #pragma unroll
    for (int i = 0; i < 8; i++) {
        m_[i] = -1e30f; l_[i] = 0.0f;
        o[i][0] = make_float2(0.f, 0.f);
        o[i][1] = make_float2(0.f, 0.f);
    }

    for (int k0 = 0; k0 < SEQ; k0 += 64) {
        __syncthreads();   // previous phase-C reads done
        // Load K transposed + V straight
        {
            const int j = t & 63, e0 = (t >> 6) * 16;
            #pragma unroll
            for (int eq = 0; eq < 16; eq += 4) {
                float4 kv = *(const float4*)&kp[(size_t)(k0 + j) * DK + e0 + eq];
                Kt[(e0 + eq + 0) * 68 + j] = kv.x;
                Kt[(e0 + eq + 1) * 68 + j] = kv.y;
                Kt[(e0 + eq + 2) * 68 + j] = kv.z;
                Kt[(e0 + eq + 3) * 68 + j] = kv.w;
                *(float4*)&Vs[j * 68 + e0 + eq] =
                    *(const float4*)&vp[(size_t)(k0 + j) * DK + e0 + eq];
            }
        }
        __syncthreads();

        // Phase A: S = Q K^T over d=0..63
        float2 s[8][2];
        #pragma unroll
        for (int i = 0; i < 8; i++) {
            s[i][0] = make_float2(0.f, 0.f);
            s[i][1] = make_float2(0.f, 0.f);
        }
        #pragma unroll 8
        for (int e = 0; e < DK; e += 2) {
            float4 ka = *(const float4*)&Kt[(e + 0) * 68 + 4 * tx];
            float4 kb = *(const float4*)&Kt[(e + 1) * 68 + 4 * tx];
            float2 ka0 = make_float2(ka.x, ka.y), ka1 = make_float2(ka.z, ka.w);
            float2 kb0 = make_float2(kb.x, kb.y), kb1 = make_float2(kb.z, kb.w);
            #pragma unroll
            for (int i = 0; i < 8; i++) {
                float2 qd = *(const float2*)&Qs[(ty + 16 * i) * 68 + e];
                float2 a0 = make_float2(qd.x, qd.x);
                float2 a1 = make_float2(qd.y, qd.y);
                s[i][0] = ffma2(a0, ka0, s[i][0]);
                s[i][1] = ffma2(a0, ka1, s[i][1]);
                s[i][0] = ffma2(a1, kb0, s[i][0]);
                s[i][1] = ffma2(a1, kb1, s[i][1]);
            }
        }

        // mask + *8 (faithful quirk) + online softmax
        #pragma unroll
        for (int i = 0; i < 8; i++) {
            const int mrow = q0 + ty + 16 * i;
            const int4 mv = *(const int4*)&mp[(size_t)mrow * SEQ + k0 + 4 * tx];
            float v0 = mv.x ? s[i][0].x * 8.0f : NEGV;
            float v1 = mv.y ? s[i][0].y * 8.0f : NEGV;
            float v2 = mv.z ? s[i][1].x * 8.0f : NEGV;
            float v3 = mv.w ? s[i][1].y * 8.0f : NEGV;

            float mt = fmaxf(fmaxf(v0, v1), fmaxf(v2, v3));
            #pragma unroll
            for (int off = 1; off < 16; off <<= 1)
                mt = fmaxf(mt, __shfl_xor_sync(0xffffffffu, mt, off));
            const float mnew  = fmaxf(m_[i], mt);
            const float scale = __expf(m_[i] - mnew);
            v0 = __expf(v0 - mnew); v1 = __expf(v1 - mnew);
            v2 = __expf(v2 - mnew); v3 = __expf(v3 - mnew);
            float rs = v0 + v1 + v2 + v3;
            #pragma unroll
            for (int off = 1; off < 16; off <<= 1)
                rs += __shfl_xor_sync(0xffffffffu, rs, off);
            l_[i] = l_[i] * scale + rs;
            m_[i] = mnew;
            const float2 sc = make_float2(scale, scale);
            o[i][0] = fmul2(o[i][0], sc);
            o[i][1] = fmul2(o[i][1], sc);

            float4 pv; pv.x = v0; pv.y = v1; pv.z = v2; pv.w = v3;
            *(float4*)&Ps[(ty + 16 * i) * 68 + 4 * tx] = pv;
        }
        __syncthreads();

        // Phase C: O += P @ V over keys e=0..63
        #pragma unroll 8
        for (int e = 0; e < 64; e += 2) {
            float4 va = *(const float4*)&Vs[(e + 0) * 68 + 4 * tx];
            float4 vb = *(const float4*)&Vs[(e + 1) * 68 + 4 * tx];
            float2 va0 = make_float2(va.x, va.y), va1 = make_float2(va.z, va.w);
            float2 vb0 = make_float2(vb.x, vb.y), vb1 = make_float2(vb.z, vb.w);
            #pragma unroll
            for (int i = 0; i < 8; i++) {
                float2 pd = *(const float2*)&Ps[(ty + 16 * i) * 68 + e];
                float2 p0 = make_float2(pd.x, pd.x);
                float2 p1 = make_float2(pd.y, pd.y);
                o[i][0] = ffma2(p0, va0, o[i][0]);
                o[i][1] = ffma2(p0, va1, o[i][1]);
                o[i][0] = ffma2(p1, vb0, o[i][0]);
                o[i][1] = ffma2(p1, vb1, o[i][1]);
            }
        }
    }

    // Epilogue: normalize + store [bh][s][d] (contiguous == reshape quirk)
    float* op = O + (size_t)bh * SEQ * DK;
    #pragma unroll
    for (int i = 0; i < 8; i++) {
        const float inv = 1.0f / l_[i];
        float4 c;
        c.x = o[i][0].x * inv; c.y = o[i][0].y * inv;
        c.z = o[i][1].x * inv; c.w = o[i][1].y * inv;
        *(float4*)&op[(size_t)(q0 + ty + 16 * i) * DK + 4 * tx] = c;
    }
}

extern "C" void kernel_launch(void* const* d_in, const int* in_sizes, int n_in,
                              void* d_out, int out_size)
{
    (void)in_sizes; (void)n_in; (void)out_size;
    const float* query  = (const float*)d_in[0];
    const float* key_in = (const float*)d_in[1];
    const float* value  = (const float*)d_in[2];
    const int*   mask   = (const int*)  d_in[3];
    const float* Wq = (const float*)d_in[4];
    const float* bq = (const float*)d_in[5];
    const float* Wk = (const float*)d_in[6];
    const float* bk = (const float*)d_in[7];
    const float* Wv = (const float*)d_in[8];
    const float* bv = (const float*)d_in[9];
    const float* Wo = (const float*)d_in[10];
    const float* bo = (const float*)d_in[11];
    float* out = (float*)d_out;

    float *qb, *kb, *vb, *ab;
    cudaGetSymbolAddress((void**)&qb, g_q);
    cudaGetSymbolAddress((void**)&kb, g_k);
    cudaGetSymbolAddress((void**)&vb, g_v);
    cudaGetSymbolAddress((void**)&ab, g_att);

    const int attn_smem = (128 + 64 + 64 + 128) * 68 * (int)sizeof(float); // 104448
    cudaFuncSetAttribute(attn_kernel,
                         cudaFuncAttributeMaxDynamicSharedMemorySize, attn_smem);

    dim3 pg(EMB / 128, (NB * SEQ) / 128);   // (4, 64)
    proj_kernel<<<pg, 256>>>(query,  Wq, bq, qb, 1);
    proj_kernel<<<pg, 256>>>(key_in, Wk, bk, kb, 1);
    proj_kernel<<<pg, 256>>>(value,  Wv, bv, vb, 1);

    dim3 ag(SEQ / 128, NB * NH);            // (16, 32)
    attn_kernel<<<ag, 256, attn_smem>>>(qb, kb, vb, mask, ab);

    proj_kernel<<<pg, 256>>>(ab, Wo, bo, out, 0);
}

// round 16
// speedup vs baseline: 2.2535x; 2.2535x over previous
#include <cuda_runtime.h>
#include <cuda_fp16.h>
#include <cstdint>

#define SEQ 2048
#define EMB 512
#define NH 8
#define DK 64
#define NB 4
#define BH (NB*NH)

#define XN ((size_t)NB*SEQ*EMB)   // 4194304
#define WN ((size_t)EMB*EMB)      // 262144
#define HN ((size_t)BH*SEQ*DK)    // 4194304

// ---------------- device scratch (allocation-free rule) ----------------
__device__ __half g_xqh[XN], g_xql[XN], g_xkh[XN], g_xkl[XN], g_xvh[XN], g_xvl[XN];
__device__ __half g_wqh[WN], g_wql[WN], g_wkh[WN], g_wkl[WN];
__device__ __half g_wvh[WN], g_wvl[WN], g_woh[WN], g_wol[WN];
__device__ __half g_qh[HN], g_ql[HN], g_kh[HN], g_kl[HN], g_vh[HN], g_vl[HN];
__device__ __half g_ah[HN], g_al[HN];
__device__ unsigned g_mbits[(size_t)NB*SEQ*(SEQ/32)];

// ---------------- helpers ----------------
__device__ __forceinline__ uint32_t smem_u32(const void* p) {
    uint32_t a;
    asm("{ .reg .u64 t; cvta.to.shared.u64 t, %1; cvt.u32.u64 %0, t; }" : "=r"(a) : "l"(p));
    return a;
}
__device__ __forceinline__ uint32_t swz(uint32_t off) { return off ^ ((off >> 3) & 0x70); }

__device__ __forceinline__ void ldm_x4(uint32_t r[4], uint32_t a) {
    asm volatile("ldmatrix.sync.aligned.m8n8.x4.shared.b16 {%0,%1,%2,%3}, [%4];"
        : "=r"(r[0]), "=r"(r[1]), "=r"(r[2]), "=r"(r[3]) : "r"(a));
}
__device__ __forceinline__ void ldm_x2(uint32_t& r0, uint32_t& r1, uint32_t a) {
    asm volatile("ldmatrix.sync.aligned.m8n8.x2.shared.b16 {%0,%1}, [%2];"
        : "=r"(r0), "=r"(r1) : "r"(a));
}
__device__ __forceinline__ void ldm_x2t(uint32_t& r0, uint32_t& r1, uint32_t a) {
    asm volatile("ldmatrix.sync.aligned.m8n8.x2.trans.shared.b16 {%0,%1}, [%2];"
        : "=r"(r0), "=r"(r1) : "r"(a));
}
__device__ __forceinline__ void mma16816(float c[4], const uint32_t a[4],
                                         uint32_t b0, uint32_t b1) {
    asm volatile("mma.sync.aligned.m16n8k16.row.col.f32.f16.f16.f32 "
        "{%0,%1,%2,%3}, {%4,%5,%6,%7}, {%8,%9}, {%0,%1,%2,%3};"
        : "+f"(c[0]), "+f"(c[1]), "+f"(c[2]), "+f"(c[3])
        : "r"(a[0]), "r"(a[1]), "r"(a[2]), "r"(a[3]), "r"(b0), "r"(b1));
}
__device__ __forceinline__ uint32_t packh2(__half lo, __half hi) {
    __half2 h = __halves2half2(lo, hi);   // .x = low 16 bits = first element
    return *(uint32_t*)&h;
}

// ---------------- conversion: f32 -> f16 hi + f16 lo ----------------
__global__ void conv_hl(const float* __restrict__ x, __half* __restrict__ h,
                        __half* __restrict__ l, int n4) {
    int i = blockIdx.x * blockDim.x + threadIdx.x;
    const int stride = gridDim.x * blockDim.x;
    for (; i < n4; i += stride) {
        float4 v = ((const float4*)x)[i];
        __half h0 = __float2half_rn(v.x), h1 = __float2half_rn(v.y);
        __half h2 = __float2half_rn(v.z), h3 = __float2half_rn(v.w);
        ((uint32_t*)h)[2*i]   = packh2(h0, h1);
        ((uint32_t*)h)[2*i+1] = packh2(h2, h3);
        __half l0 = __float2half_rn(v.x - __half2float(h0));
        __half l1 = __float2half_rn(v.y - __half2float(h1));
        __half l2 = __float2half_rn(v.z - __half2float(h2));
        __half l3 = __float2half_rn(v.w - __half2float(h3));
        ((uint32_t*)l)[2*i]   = packh2(l0, l1);
        ((uint32_t*)l)[2*i+1] = packh2(l2, l3);
    }
}

// ---------------- mask -> bitmask ----------------
__global__ void pack_mask(const int* __restrict__ mask, unsigned* __restrict__ bits) {
    const size_t w = ((size_t)blockIdx.x * blockDim.x + threadIdx.x) >> 5;
    const int lane = threadIdx.x & 31;
    const size_t base = w * 1024;
    unsigned mine = 0;
    #pragma unroll
    for (int i = 0; i < 32; i++) {
        unsigned bb = __ballot_sync(0xffffffffu, mask[base + (size_t)i * 32 + lane] != 0);
        if (lane == i) mine = bb;
    }
    bits[w * 32 + lane] = mine;
}

// ---------------------------------------------------------------------------
// HMMA projection: C[m][n] = sum_k X[m][k] W[n][k] + bias[n]
// X is read FLAT [8192 x 512] (for the O-projection this flat read of the
// [bh][s][d]-contiguous attention buffer IS the faithful reshape quirk).
// M=8192 N=512 K=512. CTA 128x128, BK=64, 8 warps (2x4), 3-term f16 split.
// outMode 0: f32 flat; outMode 1: f16 hi/lo head layout [bh][s][d], scaled.
// ---------------------------------------------------------------------------
__global__ __launch_bounds__(256) void proj_mma(
    const __half* __restrict__ Xh, const __half* __restrict__ Xl,
    const __half* __restrict__ Wh, const __half* __restrict__ Wl,
    const float* __restrict__ bias, float* __restrict__ outf,
    __half* __restrict__ oh, __half* __restrict__ ol,
    int outMode, float scale)
{
    extern __shared__ __align__(1024) char smp[];  // Xh 0 | Xl 16K | Wh 32K | Wl 48K
    const uint32_t base = smem_u32(smp);
    const int tid = threadIdx.x, wid = tid >> 5, lane = tid & 31;
    const int n0 = blockIdx.x * 128, m0 = blockIdx.y * 128;
    const int wm = wid >> 2, wn = wid & 3;

    const uint4* X4h = (const uint4*)Xh; const uint4* X4l = (const uint4*)Xl;
    const uint4* W4h = (const uint4*)Wh; const uint4* W4l = (const uint4*)Wl;

    float acc[4][4][4] = {};

    for (int kc = 0; kc < 8; kc++) {
        const int k0 = kc * 64;
        #pragma unroll
        for (int i = 0; i < 16; i++) {
            const int idx = tid + 256 * i;
            const int buf = idx >> 10, r = (idx >> 3) & 127, c = idx & 7;
            size_t src;
            const uint4* p;
            if (buf < 2) {
                src = (((size_t)(m0 + r)) * EMB + k0) >> 3;
                p = buf ? X4l : X4h;
            } else {
                src = (((size_t)(n0 + r)) * EMB + k0) >> 3;
                p = (buf == 2) ? W4h : W4l;
            }
            *(uint4*)(smp + buf * 16384 + swz(r * 128 + c * 16)) = p[src + c];
        }
        __syncthreads();
        #pragma unroll
        for (int kk = 0; kk < 4; kk++) {
            uint32_t ax[4][4], axl[4][4];
            const uint32_t arow = lane & 15, acb = lane >> 4;
            #pragma unroll
            for (int mi = 0; mi < 4; mi++) {
                const uint32_t ro = wm * 64 + mi * 16 + arow;
                const uint32_t ad = base + swz(ro * 128 + (kk * 16 + acb * 8) * 2);
                ldm_x4(ax[mi], ad);
                ldm_x4(axl[mi], ad + 16384);
            }
            uint32_t bhf[4][2], blf[4][2];
            #pragma unroll
            for (int nt = 0; nt < 4; nt++) {
                const uint32_t ro = wn * 32 + nt * 8 + (lane & 7);
                const uint32_t cb = (lane >> 3) & 1;
                const uint32_t ad = base + 32768 + swz(ro * 128 + (kk * 16 + cb * 8) * 2);
                ldm_x2(bhf[nt][0], bhf[nt][1], ad);
                ldm_x2(blf[nt][0], blf[nt][1], ad + 16384);
            }
            #pragma unroll
            for (int mi = 0; mi < 4; mi++)
                #pragma unroll
                for (int nt = 0; nt < 4; nt++) {
                    mma16816(acc[mi][nt], ax[mi],  bhf[nt][0], bhf[nt][1]);
                    mma16816(acc[mi][nt], ax[mi],  blf[nt][0], blf[nt][1]);
                    mma16816(acc[mi][nt], axl[mi], bhf[nt][0], bhf[nt][1]);
                }
        }
        __syncthreads();
    }

    // epilogue
    const int g = lane >> 2, c2 = (lane & 3) * 2;
    #pragma unroll
    for (int mi = 0; mi < 4; mi++) {
        const int mr = m0 + wm * 64 + mi * 16 + g;
        #pragma unroll
        for (int nt = 0; nt < 4; nt++) {
            const int n = n0 + wn * 32 + nt * 8 + c2;
            const float b0v = bias[n], b1v = bias[n + 1];
            float v00 = acc[mi][nt][0] + b0v, v01 = acc[mi][nt][1] + b1v;
            float v10 = acc[mi][nt][2] + b0v, v11 = acc[mi][nt][3] + b1v;
            if (outMode == 0) {
                *(float2*)&outf[(size_t)mr * EMB + n]       = make_float2(v00, v01);
                *(float2*)&outf[(size_t)(mr + 8) * EMB + n] = make_float2(v10, v11);
            } else {
                v00 *= scale; v01 *= scale; v10 *= scale; v11 *= scale;
                const int b_ = mr >> 11, ss = mr & 2047, h = n >> 6, d = n & 63;
                const size_t i0 = (((size_t)(b_ * 8 + h)) * SEQ + ss) * DK + d;
                const size_t i1 = i0 + 8 * DK;
                __half h00 = __float2half_rn(v00), h01 = __float2half_rn(v01);
                __half h10 = __float2half_rn(v10), h11 = __float2half_rn(v11);
                *(uint32_t*)(oh + i0) = packh2(h00, h01);
                *(uint32_t*)(oh + i1) = packh2(h10, h11);
                *(uint32_t*)(ol + i0) = packh2(__float2half_rn(v00 - __half2float(h00)),
                                               __float2half_rn(v01 - __half2float(h01)));
                *(uint32_t*)(ol + i1) = packh2(__float2half_rn(v10 - __half2float(h10)),
                                               __float2half_rn(v11 - __half2float(h11)));
            }
        }
    }
}

// ---------------------------------------------------------------------------
// HMMA flash attention. CTA: 128 queries, 8 warps (16 rows each), BN=64 keys.
// Q pre-scaled by 8 (quirk). Single-pass online softmax in registers.
// Output written as f16 hi/lo in [bh][s][d] (= reshape quirk for O-proj).
// ---------------------------------------------------------------------------
__global__ __launch_bounds__(256) void attn_mma(
    const __half* __restrict__ qh, const __half* __restrict__ ql,
    const __half* __restrict__ kh, const __half* __restrict__ kl,
    const __half* __restrict__ vh, const __half* __restrict__ vl,
    const unsigned* __restrict__ mbits,
    __half* __restrict__ ah, __half* __restrict__ al)
{
    __shared__ __align__(1024) char sm[32768];
    const uint32_t base = smem_u32(sm);
    const int tid = threadIdx.x, wid = tid >> 5, lane = tid & 31;
    const int bh = blockIdx.y, b = bh >> 3, q0 = blockIdx.x * 128;

    // ---- stage Q (hi 16KB @0, lo 16KB @16K), read frags, then reuse smem ----
    {
        const uint4* gq0 = (const uint4*)(qh + ((size_t)bh * SEQ + q0) * DK);
        const uint4* gq1 = (const uint4*)(ql + ((size_t)bh * SEQ + q0) * DK);
        #pragma unroll
        for (int i = 0; i < 8; i++) {
            const int idx = tid + 256 * i;
            const int buf = idx >> 10, r = (idx >> 3) & 127, c = idx & 7;
            *(uint4*)(sm + buf * 16384 + swz(r * 128 + c * 16)) =
                (buf ? gq1 : gq0)[r * 8 + c];
        }
    }
    __syncthreads();
    uint32_t aQh[4][4], aQl[4][4];
    {
        const uint32_t row = 16 * wid + (lane & 15), cb = lane >> 4;
        #pragma unroll
        for (int kk = 0; kk < 4; kk++) {
            const uint32_t ad = base + swz(row * 128 + (kk * 16 + cb * 8) * 2);
            ldm_x4(aQh[kk], ad);
            ldm_x4(aQl[kk], ad + 16384);
        }
    }

    float o[8][4] = {};
    float m_[2] = {-1e30f, -1e30f};
    float l_[2] = {0.f, 0.f};

    const uint4* gkh = (const uint4*)(kh + (size_t)bh * SEQ * DK);
    const uint4* gkl = (const uint4*)(kl + (size_t)bh * SEQ * DK);
    const uint4* gvh = (const uint4*)(vh + (size_t)bh * SEQ * DK);
    const uint4* gvl = (const uint4*)(vl + (size_t)bh * SEQ * DK);

    const int g = lane >> 2, c2 = (lane & 3) * 2;
    const size_t mrow0 = ((size_t)b * SEQ + q0 + 16 * wid + g) * 64;

    for (int j = 0; j < 32; j++) {
        __syncthreads();   // previous compute done before overwrite
        // ---- load Kh@0, Kl@8K, Vh@16K, Vl@24K (each 64x64 f16) ----
        #pragma unroll
        for (int i = 0; i < 8; i++) {
            const int idx = tid + 256 * i;
            const int buf = idx >> 9, r = (idx >> 3) & 63, c = idx & 7;
            const uint4* p = (buf == 0) ? gkh : (buf == 1) ? gkl : (buf == 2) ? gvh : gvl;
            *(uint4*)(sm + buf * 8192 + swz(r * 128 + c * 16)) = p[(j * 64 + r) * 8 + c];
        }
        __syncthreads();

        // ---- S = Q K^T (3-term) ----
        float s[8][4] = {};
        #pragma unroll
        for (int kk = 0; kk < 4; kk++) {
            #pragma unroll
            for (int nt = 0; nt < 8; nt++) {
                const uint32_t ro = nt * 8 + (lane & 7);
                const uint32_t cb = (lane >> 3) & 1;
                const uint32_t ad = base + swz(ro * 128 + (kk * 16 + cb * 8) * 2);
                uint32_t bh0, bh1, bl0, bl1;
                ldm_x2(bh0, bh1, ad);
                ldm_x2(bl0, bl1, ad + 8192);
                mma16816(s[nt], aQh[kk], bh0, bh1);
                mma16816(s[nt], aQh[kk], bl0, bl1);
                mma16816(s[nt], aQl[kk], bh0, bh1);
            }
        }

        // ---- mask + online softmax ----
        const size_t mb0 = mrow0 + j * 2;
        const uint32_t w00 = mbits[mb0],       w01 = mbits[mb0 + 1];
        const uint32_t w10 = mbits[mb0 + 512], w11 = mbits[mb0 + 513];  // row +8
        float mx0 = -1e30f, mx1 = -1e30f;
        #pragma unroll
        for (int nt = 0; nt < 8; nt++) {
            const int c = nt * 8 + c2;
            const uint32_t wa0 = (c < 32) ? w00 : w01;
            const uint32_t wa1 = (c < 32) ? w10 : w11;
            const int sh = c & 31;
            s[nt][0] = ((wa0 >> sh) & 1u)       ? s[nt][0] : -1e30f;
            s[nt][1] = ((wa0 >> (sh + 1)) & 1u) ? s[nt][1] : -1e30f;
            s[nt][2] = ((wa1 >> sh) & 1u)       ? s[nt][2] : -1e30f;
            s[nt][3] = ((wa1 >> (sh + 1)) & 1u) ? s[nt][3] : -1e30f;
            mx0 = fmaxf(mx0, fmaxf(s[nt][0], s[nt][1]));
            mx1 = fmaxf(mx1, fmaxf(s[nt][2], s[nt][3]));
        }
        mx0 = fmaxf(mx0, __shfl_xor_sync(0xffffffffu, mx0, 1));
        mx0 = fmaxf(mx0, __shfl_xor_sync(0xffffffffu, mx0, 2));
        mx1 = fmaxf(mx1, __shfl_xor_sync(0xffffffffu, mx1, 1));
        mx1 = fmaxf(mx1, __shfl_xor_sync(0xffffffffu, mx1, 2));
        const float mn0 = fmaxf(m_[0], mx0), mn1 = fmaxf(m_[1], mx1);
        const float sc0 = __expf(m_[0] - mn0), sc1 = __expf(m_[1] - mn1);
        float sum0 = 0.f, sum1 = 0.f;
        uint32_t ph[8][2], pl[8][2];
        #pragma unroll
        for (int nt = 0; nt < 8; nt++) {
            const float p0 = __expf(s[nt][0] - mn0), p1 = __expf(s[nt][1] - mn0);
            const float p2 = __expf(s[nt][2] - mn1), p3 = __expf(s[nt][3] - mn1);
            sum0 += p0 + p1; sum1 += p2 + p3;
            const __half h0 = __float2half_rn(p0), h1 = __float2half_rn(p1);
            const __half h2 = __float2half_rn(p2), h3 = __float2half_rn(p3);
            ph[nt][0] = packh2(h0, h1);
            ph[nt][1] = packh2(h2, h3);
            pl[nt][0] = packh2(__float2half_rn(p0 - __half2float(h0)),
                               __float2half_rn(p1 - __half2float(h1)));
            pl[nt][1] = packh2(__float2half_rn(p2 - __half2float(h2)),
                               __float2half_rn(p3 - __half2float(h3)));
        }
        sum0 += __shfl_xor_sync(0xffffffffu, sum0, 1);
        sum0 += __shfl_xor_sync(0xffffffffu, sum0, 2);
        sum1 += __shfl_xor_sync(0xffffffffu, sum1, 1);
        sum1 += __shfl_xor_sync(0xffffffffu, sum1, 2);
        l_[0] = l_[0] * sc0 + sum0; m_[0] = mn0;
        l_[1] = l_[1] * sc1 + sum1; m_[1] = mn1;
        #pragma unroll
        for (int dnt = 0; dnt < 8; dnt++) {
            o[dnt][0] *= sc0; o[dnt][1] *= sc0;
            o[dnt][2] *= sc1; o[dnt][3] *= sc1;
        }

        // ---- O += P V (3-term) ----
        #pragma unroll
        for (int kk = 0; kk < 4; kk++) {
            const uint32_t aPh[4] = {ph[2*kk][0], ph[2*kk][1], ph[2*kk+1][0], ph[2*kk+1][1]};
            const uint32_t aPl[4] = {pl[2*kk][0], pl[2*kk][1], pl[2*kk+1][0], pl[2*kk+1][1]};
            const uint32_t vrow = kk * 16 + (lane & 15);
            #pragma unroll
            for (int dnt = 0; dnt < 8; dnt++) {
                const uint32_t ad = base + 16384 + swz(vrow * 128 + dnt * 16);
                uint32_t bv0, bv1, bw0, bw1;
                ldm_x2t(bv0, bv1, ad);
                ldm_x2t(bw0, bw1, ad + 8192);
                mma16816(o[dnt], aPh, bv0, bv1);
                mma16816(o[dnt], aPh, bw0, bw1);
                mma16816(o[dnt], aPl, bv0, bv1);
            }
        }
    }

    // ---- epilogue: O/l -> f16 hi/lo at [bh][s][d] ----
    const float inv0 = 1.0f / l_[0], inv1 = 1.0f / l_[1];
    const size_t ro0 = ((size_t)bh * SEQ + q0 + 16 * wid + g) * DK;
    const size_t ro1 = ro0 + 8 * DK;
    #pragma unroll
    for (int dnt = 0; dnt < 8; dnt++) {
        const int col = dnt * 8 + c2;
        const float v0 = o[dnt][0] * inv0, v1 = o[dnt][1] * inv0;
        const float v2 = o[dnt][2] * inv1, v3 = o[dnt][3] * inv1;
        const __half h0 = __float2half_rn(v0), h1 = __float2half_rn(v1);
        const __half h2 = __float2half_rn(v2), h3 = __float2half_rn(v3);
        *(uint32_t*)(ah + ro0 + col) = packh2(h0, h1);
        *(uint32_t*)(ah + ro1 + col) = packh2(h2, h3);
        *(uint32_t*)(al + ro0 + col) = packh2(__float2half_rn(v0 - __half2float(h0)),
                                              __float2half_rn(v1 - __half2float(h1)));
        *(uint32_t*)(al + ro1 + col) = packh2(__float2half_rn(v2 - __half2float(h2)),
                                              __float2half_rn(v3 - __half2float(h3)));
    }
}

// ---------------------------------------------------------------------------
extern "C" void kernel_launch(void* const* d_in, const int* in_sizes, int n_in,
                              void* d_out, int out_size)
{
    (void)in_sizes; (void)n_in; (void)out_size;
    const float* query  = (const float*)d_in[0];
    const float* key_in = (const float*)d_in[1];
    const float* value  = (const float*)d_in[2];
    const int*   mask   = (const int*)  d_in[3];
    const float* Wq = (const float*)d_in[4];
    const float* bq = (const float*)d_in[5];
    const float* Wk = (const float*)d_in[6];
    const float* bk = (const float*)d_in[7];
    const float* Wv = (const float*)d_in[8];
    const float* bv = (const float*)d_in[9];
    const float* Wo = (const float*)d_in[10];
    const float* bo = (const float*)d_in[11];
    float* out = (float*)d_out;

    __half *xqh,*xql,*xkh,*xkl,*xvh,*xvl;
    __half *wqh,*wql,*wkh,*wkl,*wvh,*wvl,*woh,*wol;
    __half *qh,*ql,*kh,*kl,*vh,*vl,*ah,*al;
    unsigned* mb;
    cudaGetSymbolAddress((void**)&xqh, g_xqh); cudaGetSymbolAddress((void**)&xql, g_xql);
    cudaGetSymbolAddress((void**)&xkh, g_xkh); cudaGetSymbolAddress((void**)&xkl, g_xkl);
    cudaGetSymbolAddress((void**)&xvh, g_xvh); cudaGetSymbolAddress((void**)&xvl, g_xvl);
    cudaGetSymbolAddress((void**)&wqh, g_wqh); cudaGetSymbolAddress((void**)&wql, g_wql);
    cudaGetSymbolAddress((void**)&wkh, g_wkh); cudaGetSymbolAddress((void**)&wkl, g_wkl);
    cudaGetSymbolAddress((void**)&wvh, g_wvh); cudaGetSymbolAddress((void**)&wvl, g_wvl);
    cudaGetSymbolAddress((void**)&woh, g_woh); cudaGetSymbolAddress((void**)&wol, g_wol);
    cudaGetSymbolAddress((void**)&qh, g_qh);   cudaGetSymbolAddress((void**)&ql, g_ql);
    cudaGetSymbolAddress((void**)&kh, g_kh);   cudaGetSymbolAddress((void**)&kl, g_kl);
    cudaGetSymbolAddress((void**)&vh, g_vh);   cudaGetSymbolAddress((void**)&vl, g_vl);
    cudaGetSymbolAddress((void**)&ah, g_ah);   cudaGetSymbolAddress((void**)&al, g_al);
    cudaGetSymbolAddress((void**)&mb, g_mbits);

    cudaFuncSetAttribute(proj_mma, cudaFuncAttributeMaxDynamicSharedMemorySize, 65536);

    pack_mask<<<2048, 256>>>(mask, mb);
    conv_hl<<<1024, 256>>>(query,  xqh, xql, (int)(XN / 4));
    conv_hl<<<1024, 256>>>(key_in, xkh, xkl, (int)(XN / 4));
    conv_hl<<<1024, 256>>>(value,  xvh, xvl, (int)(XN / 4));
    conv_hl<<<256, 256>>>(Wq, wqh, wql, (int)(WN / 4));
    conv_hl<<<256, 256>>>(Wk, wkh, wkl, (int)(WN / 4));
    conv_hl<<<256, 256>>>(Wv, wvh, wvl, (int)(WN / 4));
    conv_hl<<<256, 256>>>(Wo, woh, wol, (int)(WN / 4));

    dim3 pg(EMB / 128, (NB * SEQ) / 128);   // (4, 64)
    proj_mma<<<pg, 256, 65536>>>(xqh, xql, wqh, wql, bq, nullptr, qh, ql, 1, 8.0f);
    proj_mma<<<pg, 256, 65536>>>(xkh, xkl, wkh, wkl, bk, nullptr, kh, kl, 1, 1.0f);
    proj_mma<<<pg, 256, 65536>>>(xvh, xvl, wvh, wvl, bv, nullptr, vh, vl, 1, 1.0f);

    dim3 ag(SEQ / 128, BH);                 // (16, 32)
    attn_mma<<<ag, 256>>>(qh, ql, kh, kl, vh, vl, mb, ah, al);

    proj_mma<<<pg, 256, 65536>>>(ah, al, woh, wol, bo, out, nullptr, nullptr, 0, 1.0f);
}